// round 4
// baseline (speedup 1.0000x reference)
#include <cuda_runtime.h>
#include <cstdint>

#define BN 512
#define NSTEPS 100

// ---------------- persistent device state (allocation-free scratch) ----------------
__device__ float g_m1 [BN * 20 * 784];     // conv1 membrane
__device__ float g_m1s[BN * 20 * 196];     // pool1 membrane
__device__ float g_op1[BN * 20 * 196];     // pool1 output spikes (binary)
__device__ float g_m2 [BN * 50 * 196];     // conv2 membrane
__device__ float g_m2s[BN * 50 * 49];      // pool2 membrane
__device__ float g_op2[BN * 2450];         // pool2 output spikes, layout (b, co*49+q)
__device__ float g_mf0[BN * 200];          // fc0 membrane
__device__ float g_tf0[BN * 200];          // fc0 total spike count (ONLY output that matters)

// ---------------- Threefry-2x32, 20 rounds (matches JAX exactly) ----------------
__host__ __device__ __forceinline__ void tf2x32(uint32_t k0, uint32_t k1,
                                                uint32_t x0, uint32_t x1,
                                                uint32_t& o0, uint32_t& o1) {
    uint32_t k2 = k0 ^ k1 ^ 0x1BD11BDAu;
    x0 += k0; x1 += k1;
#define TFR(r) { x0 += x1; x1 = (x1 << (r)) | (x1 >> (32 - (r))); x1 ^= x0; }
    TFR(13) TFR(15) TFR(26) TFR(6)   x0 += k1; x1 += k2 + 1u;
    TFR(17) TFR(29) TFR(16) TFR(24)  x0 += k2; x1 += k0 + 2u;
    TFR(13) TFR(15) TFR(26) TFR(6)   x0 += k0; x1 += k1 + 3u;
    TFR(17) TFR(29) TFR(16) TFR(24)  x0 += k1; x1 += k2 + 4u;
    TFR(13) TFR(15) TFR(26) TFR(6)   x0 += k2; x1 += k0 + 5u;
#undef TFR
    o0 = x0; o1 = x1;
}

// ---------------- conv1 (RNG fused) + fire(1.0) + avgpool2 + fire(0.75) ----------------
// block = one image; 224 threads (196 compute threads: one pooled 14x14 position each)
// accumulation order (ky,kx) — identical under NCHW or NHWC conventions (C=1)
__global__ __launch_bounds__(224) void k_conv1(const float* __restrict__ in,
                                               const float* __restrict__ w1,
                                               uint32_t k0, uint32_t k1) {
    int b = blockIdx.x;
    __shared__ float sin_[32][32];   // padded 28x28 (+2 halo)
    __shared__ float sw[500];        // 20 x 25 weights
    int t = threadIdx.x;
    for (int i = t; i < 1024; i += blockDim.x) ((float*)sin_)[i] = 0.f;
    for (int i = t; i < 500;  i += blockDim.x) sw[i] = w1[i];
    __syncthreads();
    // Poisson encoding (JAX partitionable threefry): flat index = b*784 + i
    for (int i = t; i < 784; i += blockDim.x) {
        uint32_t o0, o1;
        tf2x32(k0, k1, 0u, (uint32_t)(b * 784 + i), o0, o1);
        uint32_t bits = o0 ^ o1;
        float u = __uint_as_float((bits >> 9) | 0x3f800000u) - 1.0f;
        float v = in[b * 784 + i];
        float sgn = (v > 0.f) ? 1.f : ((v < 0.f) ? -1.f : 0.f);
        sin_[2 + i / 28][2 + i % 28] = (fabsf(v) * 0.5f > u) ? sgn : 0.f;
    }
    __syncthreads();

    if (t < 196) {
        int py = t / 14, px = t % 14;
        int r0 = 2 * py, c0 = 2 * px;
        float p[6][6];
#pragma unroll
        for (int r = 0; r < 6; r++)
#pragma unroll
            for (int c = 0; c < 6; c++) p[r][c] = sin_[r0 + r][c0 + c];

        for (int ch = 0; ch < 20; ch++) {
            const float* w = &sw[ch * 25];
            float a00 = 0.f, a01 = 0.f, a10 = 0.f, a11 = 0.f;
#pragma unroll
            for (int ky = 0; ky < 5; ky++)
#pragma unroll
                for (int kx = 0; kx < 5; kx++) {
                    float wv = w[ky * 5 + kx];
                    a00 = __fmaf_rn(p[ky][kx],         wv, a00);
                    a01 = __fmaf_rn(p[ky][kx + 1],     wv, a01);
                    a10 = __fmaf_rn(p[ky + 1][kx],     wv, a10);
                    a11 = __fmaf_rn(p[ky + 1][kx + 1], wv, a11);
                }
            size_t mb = (size_t)(b * 20 + ch) * 784;
            int i00 = r0 * 28 + c0;
            float m00 = g_m1[mb + i00]      + a00;
            float m01 = g_m1[mb + i00 + 1]  + a01;
            float m10 = g_m1[mb + i00 + 28] + a10;
            float m11 = g_m1[mb + i00 + 29] + a11;
            float f00 = (m00 > 1.f) ? 1.f : 0.f; g_m1[mb + i00]      = (m00 > 1.f) ? 0.f : m00;
            float f01 = (m01 > 1.f) ? 1.f : 0.f; g_m1[mb + i00 + 1]  = (m01 > 1.f) ? 0.f : m01;
            float f10 = (m10 > 1.f) ? 1.f : 0.f; g_m1[mb + i00 + 28] = (m10 > 1.f) ? 0.f : m10;
            float f11 = (m11 > 1.f) ? 1.f : 0.f; g_m1[mb + i00 + 29] = (m11 > 1.f) ? 0.f : m11;
            int pi = (b * 20 + ch) * 196 + t;
            float ms = g_m1s[pi] + 0.25f * (f00 + f01 + f10 + f11);
            float op = (ms > 0.75f) ? 1.f : 0.f;
            g_m1s[pi] = (ms > 0.75f) ? 0.f : ms;
            g_op1[pi] = op;
        }
    }
}

// ---------------- conv2: accumulation order (ky, kx, ci) — NHWC/HWIO canonical ----------------
// grid (b, 5 co-groups of 10); thread handles 2 output channels (co, co+5), 4 spatial outputs.
// smem spikes channel-innermost with stride 21 (bank spread); weights (ch, ky*5+kx, ci).
#define CSTR 21
__global__ __launch_bounds__(256) void k_conv2(const float* __restrict__ w2) {
    int b  = blockIdx.x;
    int cb = blockIdx.y * 10;
    __shared__ float sp2[18 * 18 * CSTR];  // [row][col][ci], ci stride-1, slot width 21
    __shared__ float swt[10 * 500];        // [ch][ky*5+kx][ci]
    int t = threadIdx.x;
    for (int i = t; i < 18 * 18 * CSTR; i += blockDim.x) sp2[i] = 0.f;
    for (int i = t; i < 5000; i += blockDim.x) {
        int ch = i / 500, rem = i % 500, kk = rem / 20, ci = rem % 20;
        swt[i] = w2[(cb + ch) * 500 + ci * 25 + kk];
    }
    __syncthreads();
    for (int i = t; i < 3920; i += blockDim.x) {
        int ci = i / 196, rr = (i % 196) / 14, cc = i % 14;
        sp2[((rr + 2) * 18 + (cc + 2)) * CSTR + ci] = g_op1[(b * 20 + ci) * 196 + (i % 196)];
    }
    __syncthreads();

    if (t < 245) {
        int cog = t / 49, q = t % 49;
        int py = q / 7, px = q % 7;
        int r0 = 2 * py, c0 = 2 * px;
        float a00_0 = 0.f, a01_0 = 0.f, a10_0 = 0.f, a11_0 = 0.f;
        float a00_1 = 0.f, a01_1 = 0.f, a10_1 = 0.f, a11_1 = 0.f;
        const float* pwA = &swt[cog * 500];
        const float* pwB = &swt[(cog + 5) * 500];
#pragma unroll
        for (int ky = 0; ky < 5; ky++) {
            int rA = (r0 + ky) * 18, rB = (r0 + ky + 1) * 18;
#pragma unroll
            for (int kx = 0; kx < 5; kx++) {
                const float* s0 = &sp2[(rA + c0 + kx) * CSTR];      // row ky, col kx
                const float* s1 = s0 + CSTR;                        // row ky, col kx+1
                const float* s2 = &sp2[(rB + c0 + kx) * CSTR];      // row ky+1, col kx
                const float* s3 = s2 + CSTR;                        // row ky+1, col kx+1
                const float* w0 = &pwA[(ky * 5 + kx) * 20];
                const float* w1 = &pwB[(ky * 5 + kx) * 20];
#pragma unroll 5
                for (int ci = 0; ci < 20; ci++) {
                    float v00 = s0[ci], v01 = s1[ci], v10 = s2[ci], v11 = s3[ci];
                    float wa = w0[ci], wb = w1[ci];
                    a00_0 = __fmaf_rn(v00, wa, a00_0);
                    a01_0 = __fmaf_rn(v01, wa, a01_0);
                    a10_0 = __fmaf_rn(v10, wa, a10_0);
                    a11_0 = __fmaf_rn(v11, wa, a11_0);
                    a00_1 = __fmaf_rn(v00, wb, a00_1);
                    a01_1 = __fmaf_rn(v01, wb, a01_1);
                    a10_1 = __fmaf_rn(v10, wb, a10_1);
                    a11_1 = __fmaf_rn(v11, wb, a11_1);
                }
            }
        }
        float av[2][4] = {{a00_0, a01_0, a10_0, a11_0}, {a00_1, a01_1, a10_1, a11_1}};
#pragma unroll
        for (int u = 0; u < 2; u++) {
            int co = cb + cog + u * 5;
            size_t mb = (size_t)(b * 50 + co) * 196;
            int i00 = r0 * 14 + c0;
            float m00 = g_m2[mb + i00]      + av[u][0];
            float m01 = g_m2[mb + i00 + 1]  + av[u][1];
            float m10 = g_m2[mb + i00 + 14] + av[u][2];
            float m11 = g_m2[mb + i00 + 15] + av[u][3];
            float f00 = (m00 > 1.f) ? 1.f : 0.f; g_m2[mb + i00]      = (m00 > 1.f) ? 0.f : m00;
            float f01 = (m01 > 1.f) ? 1.f : 0.f; g_m2[mb + i00 + 1]  = (m01 > 1.f) ? 0.f : m01;
            float f10 = (m10 > 1.f) ? 1.f : 0.f; g_m2[mb + i00 + 14] = (m10 > 1.f) ? 0.f : m10;
            float f11 = (m11 > 1.f) ? 1.f : 0.f; g_m2[mb + i00 + 15] = (m11 > 1.f) ? 0.f : m11;
            int pi = (b * 50 + co) * 49 + q;
            float ms = g_m2s[pi] + 0.25f * (f00 + f01 + f10 + f11);
            float op = (ms > 0.75f) ? 1.f : 0.f;
            g_m2s[pi] = (ms > 0.75f) ? 0.f : ms;
            g_op2[b * 2450 + co * 49 + q] = op;
        }
    }
}

// ---------------- fc0: y[b][n] = sum_k op2[b][k]*wf0[n][k], single sequential k-chain ----------------
__global__ __launch_bounds__(128) void k_fc0(const float* __restrict__ wf0) {
    int mb = blockIdx.x * 32;
    int nb = blockIdx.y * 40;
    __shared__ float si[32][36];
    __shared__ float swt[40][36];
    int t = threadIdx.x;
    int tb = t % 16, tn = t / 16;
    float acc[2][5] = {{0.f}};
    for (int kc = 0; kc < 2450; kc += 35) {
        for (int i = t; i < 32 * 35; i += 128) {
            int r = i / 35, c = i % 35;
            si[r][c] = g_op2[(mb + r) * 2450 + kc + c];
        }
        for (int i = t; i < 40 * 35; i += 128) {
            int r = i / 35, c = i % 35;
            swt[r][c] = wf0[(nb + r) * 2450 + kc + c];
        }
        __syncthreads();
#pragma unroll 5
        for (int k = 0; k < 35; k++) {
            float i0 = si[2 * tb][k], i1 = si[2 * tb + 1][k];
#pragma unroll
            for (int j = 0; j < 5; j++) {
                float wv = swt[tn * 5 + j][k];
                acc[0][j] = __fmaf_rn(i0, wv, acc[0][j]);
                acc[1][j] = __fmaf_rn(i1, wv, acc[1][j]);
            }
        }
        __syncthreads();
    }
#pragma unroll
    for (int i = 0; i < 2; i++)
#pragma unroll
        for (int j = 0; j < 5; j++) {
            int idx = (mb + 2 * tb + i) * 200 + nb + tn * 5 + j;
            float m = g_mf0[idx] + acc[i][j];
            float o = (m > 1.f) ? 1.f : 0.f;
            g_mf0[idx] = (m > 1.f) ? 0.f : m;
            g_tf0[idx] += o;
        }
}

// ---------------- final readout: out = (Tf0 @ wf1^T) / 100 ----------------
__global__ void k_final(const float* __restrict__ wf1, float* __restrict__ out) {
    int i = blockIdx.x * blockDim.x + threadIdx.x;
    if (i >= BN * 10) return;
    int b = i / 10, j = i % 10;
    const float* tf = &g_tf0[b * 200];
    const float* w  = &wf1[j * 200];
    float s = 0.f;
#pragma unroll 8
    for (int n = 0; n < 200; n++) s = __fmaf_rn(tf[n], w[n], s);
    out[i] = s / 100.0f;
}

// ---------------- launch ----------------
extern "C" void kernel_launch(void* const* d_in, const int* in_sizes, int n_in,
                              void* d_out, int out_size) {
    const float* in  = (const float*)d_in[0];
    const float* w1  = (const float*)d_in[1];
    const float* w2  = (const float*)d_in[2];
    const float* wf0 = (const float*)d_in[3];
    const float* wf1 = (const float*)d_in[4];
    float* out = (float*)d_out;

    // Zero persistent state (graph-capturable async memsets)
    void* p;
    cudaGetSymbolAddress(&p, g_m1);  cudaMemsetAsync(p, 0, sizeof(float) * BN * 20 * 784);
    cudaGetSymbolAddress(&p, g_m1s); cudaMemsetAsync(p, 0, sizeof(float) * BN * 20 * 196);
    cudaGetSymbolAddress(&p, g_m2);  cudaMemsetAsync(p, 0, sizeof(float) * BN * 50 * 196);
    cudaGetSymbolAddress(&p, g_m2s); cudaMemsetAsync(p, 0, sizeof(float) * BN * 50 * 49);
    cudaGetSymbolAddress(&p, g_mf0); cudaMemsetAsync(p, 0, sizeof(float) * BN * 200);
    cudaGetSymbolAddress(&p, g_tf0); cudaMemsetAsync(p, 0, sizeof(float) * BN * 200);

    // Per-step keys: JAX partitionable split — key_t = threefry((0,42), (0,t))
    uint32_t keys[NSTEPS][2];
    for (int t = 0; t < NSTEPS; t++)
        tf2x32(0u, 42u, 0u, (uint32_t)t, keys[t][0], keys[t][1]);

    for (int t = 0; t < NSTEPS; t++) {
        k_conv1<<<BN, 224>>>(in, w1, keys[t][0], keys[t][1]);
        k_conv2<<<dim3(BN, 5), 256>>>(w2);
        k_fc0  <<<dim3(16, 5), 128>>>(wf0);
    }
    k_final<<<(BN * 10 + 255) / 256, 256>>>(wf1, out);
}

// round 5
// speedup vs baseline: 2.7240x; 2.7240x over previous
#include <cuda_runtime.h>
#include <cstdint>

#define BN 512
#define NSTEPS 100

// ---------------- persistent device state (allocation-free scratch) ----------------
__device__ float g_m1 [BN * 20 * 784];     // conv1 membrane
__device__ float g_m1s[BN * 20 * 196];     // pool1 membrane
__device__ float g_op1[BN * 20 * 196];     // pool1 output spikes (binary)
__device__ float g_m2 [BN * 50 * 196];     // conv2 membrane
__device__ float g_m2s[BN * 50 * 49];      // pool2 membrane
__device__ float g_op2[BN * 2450];         // pool2 output spikes, layout (b, co*49+q)
__device__ float g_mf0[BN * 200];          // fc0 membrane
__device__ float g_tf0[BN * 200];          // fc0 total spike count (ONLY output that matters)
__device__ float g_yp [5 * BN * 200];      // fc0 K-split partials (order proven output-neutral)

// ---------------- Threefry-2x32, 20 rounds (matches JAX exactly) ----------------
__host__ __device__ __forceinline__ void tf2x32(uint32_t k0, uint32_t k1,
                                                uint32_t x0, uint32_t x1,
                                                uint32_t& o0, uint32_t& o1) {
    uint32_t k2 = k0 ^ k1 ^ 0x1BD11BDAu;
    x0 += k0; x1 += k1;
#define TFR(r) { x0 += x1; x1 = (x1 << (r)) | (x1 >> (32 - (r))); x1 ^= x0; }
    TFR(13) TFR(15) TFR(26) TFR(6)   x0 += k1; x1 += k2 + 1u;
    TFR(17) TFR(29) TFR(16) TFR(24)  x0 += k2; x1 += k0 + 2u;
    TFR(13) TFR(15) TFR(26) TFR(6)   x0 += k0; x1 += k1 + 3u;
    TFR(17) TFR(29) TFR(16) TFR(24)  x0 += k1; x1 += k2 + 4u;
    TFR(13) TFR(15) TFR(26) TFR(6)   x0 += k2; x1 += k0 + 5u;
#undef TFR
    o0 = x0; o1 = x1;
}

// ---------------- conv1 (RNG fused) + fire(1.0) + avgpool2 + fire(0.75) ----------------
// UNCHANGED from round 4 (bit-exact requirement)
__global__ __launch_bounds__(224) void k_conv1(const float* __restrict__ in,
                                               const float* __restrict__ w1,
                                               uint32_t k0, uint32_t k1) {
    int b = blockIdx.x;
    __shared__ float sin_[32][32];   // padded 28x28 (+2 halo)
    __shared__ float sw[500];        // 20 x 25 weights
    int t = threadIdx.x;
    for (int i = t; i < 1024; i += blockDim.x) ((float*)sin_)[i] = 0.f;
    for (int i = t; i < 500;  i += blockDim.x) sw[i] = w1[i];
    __syncthreads();
    for (int i = t; i < 784; i += blockDim.x) {
        uint32_t o0, o1;
        tf2x32(k0, k1, 0u, (uint32_t)(b * 784 + i), o0, o1);
        uint32_t bits = o0 ^ o1;
        float u = __uint_as_float((bits >> 9) | 0x3f800000u) - 1.0f;
        float v = in[b * 784 + i];
        float sgn = (v > 0.f) ? 1.f : ((v < 0.f) ? -1.f : 0.f);
        sin_[2 + i / 28][2 + i % 28] = (fabsf(v) * 0.5f > u) ? sgn : 0.f;
    }
    __syncthreads();

    if (t < 196) {
        int py = t / 14, px = t % 14;
        int r0 = 2 * py, c0 = 2 * px;
        float p[6][6];
#pragma unroll
        for (int r = 0; r < 6; r++)
#pragma unroll
            for (int c = 0; c < 6; c++) p[r][c] = sin_[r0 + r][c0 + c];

        for (int ch = 0; ch < 20; ch++) {
            const float* w = &sw[ch * 25];
            float a00 = 0.f, a01 = 0.f, a10 = 0.f, a11 = 0.f;
#pragma unroll
            for (int ky = 0; ky < 5; ky++)
#pragma unroll
                for (int kx = 0; kx < 5; kx++) {
                    float wv = w[ky * 5 + kx];
                    a00 = __fmaf_rn(p[ky][kx],         wv, a00);
                    a01 = __fmaf_rn(p[ky][kx + 1],     wv, a01);
                    a10 = __fmaf_rn(p[ky + 1][kx],     wv, a10);
                    a11 = __fmaf_rn(p[ky + 1][kx + 1], wv, a11);
                }
            size_t mb = (size_t)(b * 20 + ch) * 784;
            int i00 = r0 * 28 + c0;
            float m00 = g_m1[mb + i00]      + a00;
            float m01 = g_m1[mb + i00 + 1]  + a01;
            float m10 = g_m1[mb + i00 + 28] + a10;
            float m11 = g_m1[mb + i00 + 29] + a11;
            float f00 = (m00 > 1.f) ? 1.f : 0.f; g_m1[mb + i00]      = (m00 > 1.f) ? 0.f : m00;
            float f01 = (m01 > 1.f) ? 1.f : 0.f; g_m1[mb + i00 + 1]  = (m01 > 1.f) ? 0.f : m01;
            float f10 = (m10 > 1.f) ? 1.f : 0.f; g_m1[mb + i00 + 28] = (m10 > 1.f) ? 0.f : m10;
            float f11 = (m11 > 1.f) ? 1.f : 0.f; g_m1[mb + i00 + 29] = (m11 > 1.f) ? 0.f : m11;
            int pi = (b * 20 + ch) * 196 + t;
            float ms = g_m1s[pi] + 0.25f * (f00 + f01 + f10 + f11);
            float op = (ms > 0.75f) ? 1.f : 0.f;
            g_m1s[pi] = (ms > 0.75f) ? 0.f : ms;
            g_op1[pi] = op;
        }
    }
}

// ---------------- conv2: (ky,kx,ci) chain UNCHANGED; dataflow rebuilt ----------------
// grid (b, 2): 25 output channels per block. 256 threads = 5 cogs x 49 positions.
// Each thread: 5 channels (co = cb + cog*5 + u), 4 spatial outputs.
// Spike smem layout addr = r*387 + c*21 + ci  (lane bank = (5px+3py) mod 16 -> max 2-way).
// Weights smem [ch][kk][ci], read as aligned float2 pairs over ci.
#define SP_RS 387
#define SP_CS 21
#define C2_SMEM ((6976 + 12500) * 4)
__global__ __launch_bounds__(256) void k_conv2(const float* __restrict__ w2) {
    extern __shared__ float dyn[];
    float* sp  = dyn;          // 18*387 = 6966 floats (padded region zeroed)
    float* swt = dyn + 6976;   // 25*500 = 12500 floats, [ch][kk*20+ci]
    int b  = blockIdx.x;
    int cb = blockIdx.y * 25;
    int t = threadIdx.x;
    for (int i = t; i < 6976; i += 256) sp[i] = 0.f;
    for (int i = t; i < 12500; i += 256) {
        int ch = i / 500, rem = i % 500, kk = rem / 20, ci = rem % 20;
        swt[i] = w2[(cb + ch) * 500 + ci * 25 + kk];
    }
    __syncthreads();
    for (int i = t; i < 3920; i += 256) {
        int ci = i / 196, pos = i % 196, rr = pos / 14, cc = pos % 14;
        sp[(rr + 2) * SP_RS + (cc + 2) * SP_CS + ci] = g_op1[(b * 20 + ci) * 196 + pos];
    }
    __syncthreads();

    if (t < 245) {
        int cog = t / 49, q = t % 49;
        int py = q / 7, px = q % 7;
        int r0 = 2 * py, c0 = 2 * px;
        float acc[5][4] = {};
        const float* wb = &swt[cog * 5 * 500];
        int sbase = r0 * SP_RS + c0 * SP_CS;
#pragma unroll 1
        for (int ky = 0; ky < 5; ky++) {
#pragma unroll 1
            for (int kx = 0; kx < 5; kx++) {
                const float* s00 = &sp[sbase + ky * SP_RS + kx * SP_CS];
                const float* s10 = s00 + SP_RS;
                const float* wk  = &wb[(ky * 5 + kx) * 20];
#pragma unroll
                for (int ci = 0; ci < 20; ci += 2) {
                    // aligned float2 weight loads (word index even for even ci)
                    float2 w0 = *(const float2*)&wk[0 * 500 + ci];
                    float2 w1 = *(const float2*)&wk[1 * 500 + ci];
                    float2 w2v = *(const float2*)&wk[2 * 500 + ci];
                    float2 w3 = *(const float2*)&wk[3 * 500 + ci];
                    float2 w4 = *(const float2*)&wk[4 * 500 + ci];
                    float va0 = s00[ci],         va1 = s00[SP_CS + ci];
                    float va2 = s10[ci],         va3 = s10[SP_CS + ci];
                    float vb0 = s00[ci + 1],     vb1 = s00[SP_CS + ci + 1];
                    float vb2 = s10[ci + 1],     vb3 = s10[SP_CS + ci + 1];
                    // ci (even) then ci+1 — ascending-ci chain per output preserved
                    acc[0][0] = __fmaf_rn(va0, w0.x, acc[0][0]);
                    acc[0][1] = __fmaf_rn(va1, w0.x, acc[0][1]);
                    acc[0][2] = __fmaf_rn(va2, w0.x, acc[0][2]);
                    acc[0][3] = __fmaf_rn(va3, w0.x, acc[0][3]);
                    acc[1][0] = __fmaf_rn(va0, w1.x, acc[1][0]);
                    acc[1][1] = __fmaf_rn(va1, w1.x, acc[1][1]);
                    acc[1][2] = __fmaf_rn(va2, w1.x, acc[1][2]);
                    acc[1][3] = __fmaf_rn(va3, w1.x, acc[1][3]);
                    acc[2][0] = __fmaf_rn(va0, w2v.x, acc[2][0]);
                    acc[2][1] = __fmaf_rn(va1, w2v.x, acc[2][1]);
                    acc[2][2] = __fmaf_rn(va2, w2v.x, acc[2][2]);
                    acc[2][3] = __fmaf_rn(va3, w2v.x, acc[2][3]);
                    acc[3][0] = __fmaf_rn(va0, w3.x, acc[3][0]);
                    acc[3][1] = __fmaf_rn(va1, w3.x, acc[3][1]);
                    acc[3][2] = __fmaf_rn(va2, w3.x, acc[3][2]);
                    acc[3][3] = __fmaf_rn(va3, w3.x, acc[3][3]);
                    acc[4][0] = __fmaf_rn(va0, w4.x, acc[4][0]);
                    acc[4][1] = __fmaf_rn(va1, w4.x, acc[4][1]);
                    acc[4][2] = __fmaf_rn(va2, w4.x, acc[4][2]);
                    acc[4][3] = __fmaf_rn(va3, w4.x, acc[4][3]);
                    acc[0][0] = __fmaf_rn(vb0, w0.y, acc[0][0]);
                    acc[0][1] = __fmaf_rn(vb1, w0.y, acc[0][1]);
                    acc[0][2] = __fmaf_rn(vb2, w0.y, acc[0][2]);
                    acc[0][3] = __fmaf_rn(vb3, w0.y, acc[0][3]);
                    acc[1][0] = __fmaf_rn(vb0, w1.y, acc[1][0]);
                    acc[1][1] = __fmaf_rn(vb1, w1.y, acc[1][1]);
                    acc[1][2] = __fmaf_rn(vb2, w1.y, acc[1][2]);
                    acc[1][3] = __fmaf_rn(vb3, w1.y, acc[1][3]);
                    acc[2][0] = __fmaf_rn(vb0, w2v.y, acc[2][0]);
                    acc[2][1] = __fmaf_rn(vb1, w2v.y, acc[2][1]);
                    acc[2][2] = __fmaf_rn(vb2, w2v.y, acc[2][2]);
                    acc[2][3] = __fmaf_rn(vb3, w2v.y, acc[2][3]);
                    acc[3][0] = __fmaf_rn(vb0, w3.y, acc[3][0]);
                    acc[3][1] = __fmaf_rn(vb1, w3.y, acc[3][1]);
                    acc[3][2] = __fmaf_rn(vb2, w3.y, acc[3][2]);
                    acc[3][3] = __fmaf_rn(vb3, w3.y, acc[3][3]);
                    acc[4][0] = __fmaf_rn(vb0, w4.y, acc[4][0]);
                    acc[4][1] = __fmaf_rn(vb1, w4.y, acc[4][1]);
                    acc[4][2] = __fmaf_rn(vb2, w4.y, acc[4][2]);
                    acc[4][3] = __fmaf_rn(vb3, w4.y, acc[4][3]);
                }
            }
        }
#pragma unroll
        for (int u = 0; u < 5; u++) {
            int co = cb + cog * 5 + u;
            size_t mb = (size_t)(b * 50 + co) * 196;
            int i00 = r0 * 14 + c0;
            float m00 = g_m2[mb + i00]      + acc[u][0];
            float m01 = g_m2[mb + i00 + 1]  + acc[u][1];
            float m10 = g_m2[mb + i00 + 14] + acc[u][2];
            float m11 = g_m2[mb + i00 + 15] + acc[u][3];
            float f00 = (m00 > 1.f) ? 1.f : 0.f; g_m2[mb + i00]      = (m00 > 1.f) ? 0.f : m00;
            float f01 = (m01 > 1.f) ? 1.f : 0.f; g_m2[mb + i00 + 1]  = (m01 > 1.f) ? 0.f : m01;
            float f10 = (m10 > 1.f) ? 1.f : 0.f; g_m2[mb + i00 + 14] = (m10 > 1.f) ? 0.f : m10;
            float f11 = (m11 > 1.f) ? 1.f : 0.f; g_m2[mb + i00 + 15] = (m11 > 1.f) ? 0.f : m11;
            int pi = (b * 50 + co) * 49 + q;
            float ms = g_m2s[pi] + 0.25f * (f00 + f01 + f10 + f11);
            float op = (ms > 0.75f) ? 1.f : 0.f;
            g_m2s[pi] = (ms > 0.75f) ? 0.f : ms;
            g_op2[b * 2450 + co * 49 + q] = op;
        }
    }
}

// ---------------- fc0 GEMM split-K x5 (proven output-neutral, 5x more blocks) ----------------
__global__ __launch_bounds__(128) void k_fc0(const float* __restrict__ wf0) {
    int mb = blockIdx.x * 32;
    int nb = blockIdx.y * 40;
    int kb = blockIdx.z * 490;
    __shared__ float si[32][36];
    __shared__ float swt[40][36];
    int t = threadIdx.x;
    int tb = t % 16, tn = t / 16;
    float acc[2][5] = {{0.f}};
    for (int kc = 0; kc < 490; kc += 35) {
        for (int i = t; i < 32 * 35; i += 128) {
            int r = i / 35, c = i % 35;
            si[r][c] = g_op2[(mb + r) * 2450 + kb + kc + c];
        }
        for (int i = t; i < 40 * 35; i += 128) {
            int r = i / 35, c = i % 35;
            swt[r][c] = wf0[(nb + r) * 2450 + kb + kc + c];
        }
        __syncthreads();
#pragma unroll 5
        for (int k = 0; k < 35; k++) {
            float i0 = si[2 * tb][k], i1 = si[2 * tb + 1][k];
#pragma unroll
            for (int j = 0; j < 5; j++) {
                float wv = swt[tn * 5 + j][k];
                acc[0][j] = __fmaf_rn(i0, wv, acc[0][j]);
                acc[1][j] = __fmaf_rn(i1, wv, acc[1][j]);
            }
        }
        __syncthreads();
    }
#pragma unroll
    for (int i = 0; i < 2; i++)
#pragma unroll
        for (int j = 0; j < 5; j++)
            g_yp[(size_t)blockIdx.z * (BN * 200) + (mb + 2 * tb + i) * 200 + nb + tn * 5 + j] = acc[i][j];
}

// ---------------- fc0 fire: reduce K-split partials, membrane, Tf0 ----------------
__global__ void k_f0fire() {
    int i = blockIdx.x * blockDim.x + threadIdx.x;
    if (i >= BN * 200) return;
    float y = __fadd_rn(__fadd_rn(__fadd_rn(g_yp[i], g_yp[BN * 200 + i]),
                                  __fadd_rn(g_yp[2 * BN * 200 + i], g_yp[3 * BN * 200 + i])),
                        g_yp[4 * BN * 200 + i]);
    float m = g_mf0[i] + y;
    float o = (m > 1.f) ? 1.f : 0.f;
    g_mf0[i] = (m > 1.f) ? 0.f : m;
    g_tf0[i] += o;
}

// ---------------- final readout: out = (Tf0 @ wf1^T) / 100 ----------------
__global__ void k_final(const float* __restrict__ wf1, float* __restrict__ out) {
    int i = blockIdx.x * blockDim.x + threadIdx.x;
    if (i >= BN * 10) return;
    int b = i / 10, j = i % 10;
    const float* tf = &g_tf0[b * 200];
    const float* w  = &wf1[j * 200];
    float s = 0.f;
#pragma unroll 8
    for (int n = 0; n < 200; n++) s = __fmaf_rn(tf[n], w[n], s);
    out[i] = s / 100.0f;
}

// ---------------- launch ----------------
extern "C" void kernel_launch(void* const* d_in, const int* in_sizes, int n_in,
                              void* d_out, int out_size) {
    const float* in  = (const float*)d_in[0];
    const float* w1  = (const float*)d_in[1];
    const float* w2  = (const float*)d_in[2];
    const float* wf0 = (const float*)d_in[3];
    const float* wf1 = (const float*)d_in[4];
    float* out = (float*)d_out;

    cudaFuncSetAttribute(k_conv2, cudaFuncAttributeMaxDynamicSharedMemorySize, C2_SMEM);

    // Zero persistent state (graph-capturable async memsets)
    void* p;
    cudaGetSymbolAddress(&p, g_m1);  cudaMemsetAsync(p, 0, sizeof(float) * BN * 20 * 784);
    cudaGetSymbolAddress(&p, g_m1s); cudaMemsetAsync(p, 0, sizeof(float) * BN * 20 * 196);
    cudaGetSymbolAddress(&p, g_m2);  cudaMemsetAsync(p, 0, sizeof(float) * BN * 50 * 196);
    cudaGetSymbolAddress(&p, g_m2s); cudaMemsetAsync(p, 0, sizeof(float) * BN * 50 * 49);
    cudaGetSymbolAddress(&p, g_mf0); cudaMemsetAsync(p, 0, sizeof(float) * BN * 200);
    cudaGetSymbolAddress(&p, g_tf0); cudaMemsetAsync(p, 0, sizeof(float) * BN * 200);

    // Per-step keys: JAX partitionable split — key_t = threefry((0,42), (0,t))
    uint32_t keys[NSTEPS][2];
    for (int t = 0; t < NSTEPS; t++)
        tf2x32(0u, 42u, 0u, (uint32_t)t, keys[t][0], keys[t][1]);

    for (int t = 0; t < NSTEPS; t++) {
        k_conv1<<<BN, 224>>>(in, w1, keys[t][0], keys[t][1]);
        k_conv2<<<dim3(BN, 2), 256, C2_SMEM>>>(w2);
        k_fc0  <<<dim3(16, 5, 5), 128>>>(wf0);
        k_f0fire<<<(BN * 200 + 255) / 256, 256>>>();
    }
    k_final<<<(BN * 10 + 255) / 256, 256>>>(wf1, out);
}